// round 2
// baseline (speedup 1.0000x reference)
#include <cuda_runtime.h>
#include <math.h>

#define I_SIZE 256
#define N_NEURONS 1024
#define N_DIMS 64
#define D_FEAT 128
#define T_STEPS 256   // = O_SIZE, only first 256 scan steps are observable

// scratch: w_t for all 256 steps (128 KB)
__device__ float g_w[T_STEPS * D_FEAT];

// ---------------------------------------------------------------------------
// Kernel B: the serial recurrence.
//   v_0[j]   = s0 * u[j],  s0 = (sum_k<256 pos_tail[k]) . pos_head[0],
//                          u[j] = sum_i x[i,j]
//   w_t      = v_t @ W_t
//   v_{t+1}  = tanh(a[t][t+1] * w_t)
// Single CTA, 512 threads: warp = one k-group of 8 rows, lanes cover j in
// float4 quads (fully coalesced 512B/warp loads of W).
// ---------------------------------------------------------------------------
__global__ __launch_bounds__(512, 1) void recur_kernel(
    const float* __restrict__ x, const float* __restrict__ pos_head,
    const float* __restrict__ pos_tail, const float* __restrict__ W,
    const float* __restrict__ a)
{
    __shared__ float sh_v[D_FEAT];
    __shared__ float sh_part[16 * D_FEAT];
    __shared__ float sh_alpha[T_STEPS];
    __shared__ float sh_T[N_DIMS];
    __shared__ float sh_s0;

    const int tid = threadIdx.x;

    // --- one-time init ---
    if (tid < T_STEPS) {
        // alpha_t = a[t][t+1] (t=255 value unused but harmless)
        sh_alpha[tid] = a[(size_t)tid * N_NEURONS + tid + 1];
    }
    if (tid < N_DIMS) {
        float s = 0.f;
        #pragma unroll 4
        for (int k = 0; k < I_SIZE; k++) s += pos_tail[k * N_DIMS + tid];
        sh_T[tid] = s;
    }
    __syncthreads();
    if (tid < 32) {
        float p = sh_T[tid] * pos_head[tid] + sh_T[tid + 32] * pos_head[tid + 32];
        #pragma unroll
        for (int off = 16; off > 0; off >>= 1)
            p += __shfl_xor_sync(0xffffffffu, p, off);
        if (tid == 0) sh_s0 = p;
    }
    __syncthreads();
    if (tid < D_FEAT) {
        float u = 0.f;
        #pragma unroll 4
        for (int i = 0; i < I_SIZE; i++) u += x[i * D_FEAT + tid];
        sh_v[tid] = sh_s0 * u;
    }
    __syncthreads();

    const int jq = tid & 31;   // j quad: covers j = 4*jq .. 4*jq+3
    const int kg = tid >> 5;   // k group: rows kg*8 .. kg*8+7 (one warp per group)

    for (int t = 0; t < T_STEPS; t++) {
        const float* Wt = W + (size_t)t * (D_FEAT * D_FEAT);
        float4 acc = make_float4(0.f, 0.f, 0.f, 0.f);
        #pragma unroll
        for (int r = 0; r < 8; r++) {
            const int k = kg * 8 + r;
            const float vk = sh_v[k];                      // warp-broadcast LDS
            const float4 wv = *(const float4*)(Wt + k * D_FEAT + 4 * jq);
            acc.x = fmaf(vk, wv.x, acc.x);
            acc.y = fmaf(vk, wv.y, acc.y);
            acc.z = fmaf(vk, wv.z, acc.z);
            acc.w = fmaf(vk, wv.w, acc.w);
        }
        *(float4*)(&sh_part[kg * D_FEAT + 4 * jq]) = acc;
        __syncthreads();   // all reads of sh_v for this step done; partials visible

        if (tid < D_FEAT) {
            float s = 0.f;
            #pragma unroll
            for (int g = 0; g < 16; g++) s += sh_part[g * D_FEAT + tid];
            g_w[t * D_FEAT + tid] = s;
            sh_v[tid] = tanhf(sh_alpha[t] * s);
        }
        __syncthreads();   // v_{t+1} visible before next step's loads
    }
}

// ---------------------------------------------------------------------------
// Kernel C: out[t, l, j] = tanh(a[t][l] * w_t[j])
// 2048 blocks x 256 threads: block = (t, 128-row slab of l). 128 MB of
// float4 stores -> HBM-write bound.
// ---------------------------------------------------------------------------
__global__ __launch_bounds__(256, 8) void outer_kernel(
    const float* __restrict__ a, float* __restrict__ out)
{
    __shared__ float wsh[D_FEAT];
    const int bid = blockIdx.x;
    const int t  = bid >> 3;
    const int lb = (bid & 7) << 7;   // *128
    const int tid = threadIdx.x;

    if (tid < D_FEAT) wsh[tid] = g_w[t * D_FEAT + tid];
    __syncthreads();

    const float* __restrict__ arow = a + (size_t)t * N_NEURONS + lb;
    float* __restrict__ obase = out + ((size_t)t * N_NEURONS + lb) * D_FEAT;

    #pragma unroll
    for (int it = 0; it < 16; it++) {
        const int item = it * 256 + tid;     // 0..4095 over (l_local, jq)
        const int ll = item >> 5;            // l within slab (warp-uniform)
        const int jq = item & 31;            // j quad (lane id)
        const float av = arow[ll];
        const float4 wv = *(const float4*)(&wsh[4 * jq]);
        float4 o;
        o.x = tanhf(av * wv.x);
        o.y = tanhf(av * wv.y);
        o.z = tanhf(av * wv.z);
        o.w = tanhf(av * wv.w);
        *(float4*)(obase + ll * D_FEAT + 4 * jq) = o;
    }
}

extern "C" void kernel_launch(void* const* d_in, const int* in_sizes, int n_in,
                              void* d_out, int out_size)
{
    const float* x        = (const float*)d_in[0];   // (256, 128)
    const float* pos_head = (const float*)d_in[1];   // (1024, 64)
    const float* pos_tail = (const float*)d_in[2];   // (1024, 64)
    const float* W        = (const float*)d_in[3];   // (768, 128, 128)
    const float* a        = (const float*)d_in[4];   // (768, 1024)
    float* out            = (float*)d_out;           // (256, 1024, 128)

    recur_kernel<<<1, 512>>>(x, pos_head, pos_tail, W, a);
    outer_kernel<<<T_STEPS * 8, 256>>>(a, out);
}